// round 3
// baseline (speedup 1.0000x reference)
#include <cuda_runtime.h>
#include <cmath>

#define BSZ   2048          // B_DAYS * STOCKS
#define TT    60
#define HID   256
#define G3    768           // 3*HID
#define DF    6
#define NSAMP 20480         // 4 * K_DAY * STOCKS
#define NDAYS 240
#define KDAY  10
#define NNB   10

// ---------------- device scratch (no allocations allowed) ----------------
__device__ float g_h[BSZ * HID];
__device__ float g_gh[BSZ * G3];
__device__ float g_hs[BSZ * TT * HID];        // layer-0 hidden sequence (126 MB)
__device__ float g_xw1[(size_t)BSZ * TT * G3];// layer-1 input gates (377 MB)
__device__ float g_mb1[BSZ * 512];
__device__ float g_mb2[BSZ * 512];
__device__ float g_mb[BSZ * HID];
__device__ float g_mbday[4 * HID];
__device__ int   g_dayidx[4 * KDAY];
__device__ int   g_rowmap[NSAMP];
__device__ float g_kh[NSAMP * HID];
__device__ float g_khn[NSAMP];
__device__ float g_q[BSZ * HID];
__device__ float g_qn[BSZ];
__device__ float g_cs[(size_t)BSZ * NSAMP];   // 168 MB
__device__ float g_vals[BSZ * NNB];
__device__ int   g_nidx[BSZ * NNB];

// ---------------- generic fp32 GEMM: C[M,N] = A[M,K] @ B[N,K]^T ----------------
// act: 0 = none, 1 = leaky(0.01), 2 = cosine-normalize by rnorm[m]*cnorm[n]
// rowmap: optional gather of A rows. Requires M%64==0, N%64==0, K%16==0.
#define BM 64
#define BN 64
#define BK 16

__global__ void gemm_tn(const float* __restrict__ A, const float* __restrict__ B,
                        const float* __restrict__ bias, float* __restrict__ C,
                        int M, int N, int K, int act,
                        const int* __restrict__ rowmap,
                        const float* __restrict__ rnorm, const float* __restrict__ cnorm)
{
    __shared__ float As[BK][BM];
    __shared__ float Bs[BK][BN];
    const int bm = blockIdx.y * BM;
    const int bn = blockIdx.x * BN;
    const int tid = threadIdx.x;                 // 256 threads
    const int lr = tid >> 2;                     // 0..63  (load row)
    const int lc = (tid & 3) * 4;                // 0,4,8,12 (load col group)
    const int tm = (tid >> 4) * 4;               // compute row base
    const int tn = (tid & 15) * 4;               // compute col base

    int arow = bm + lr;
    if (rowmap) arow = rowmap[arow];
    const float* Ar = A + (size_t)arow * K;
    const float* Br = B + (size_t)(bn + lr) * K;

    float acc[4][4] = {};

    for (int k0 = 0; k0 < K; k0 += BK) {
        float4 av = *(const float4*)(Ar + k0 + lc);
        float4 bv = *(const float4*)(Br + k0 + lc);
        As[lc + 0][lr] = av.x; As[lc + 1][lr] = av.y;
        As[lc + 2][lr] = av.z; As[lc + 3][lr] = av.w;
        Bs[lc + 0][lr] = bv.x; Bs[lc + 1][lr] = bv.y;
        Bs[lc + 2][lr] = bv.z; Bs[lc + 3][lr] = bv.w;
        __syncthreads();
        #pragma unroll
        for (int kk = 0; kk < BK; kk++) {
            float4 a = *(const float4*)&As[kk][tm];
            float4 b = *(const float4*)&Bs[kk][tn];
            acc[0][0] += a.x * b.x; acc[0][1] += a.x * b.y; acc[0][2] += a.x * b.z; acc[0][3] += a.x * b.w;
            acc[1][0] += a.y * b.x; acc[1][1] += a.y * b.y; acc[1][2] += a.y * b.z; acc[1][3] += a.y * b.w;
            acc[2][0] += a.z * b.x; acc[2][1] += a.z * b.y; acc[2][2] += a.z * b.z; acc[2][3] += a.z * b.w;
            acc[3][0] += a.w * b.x; acc[3][1] += a.w * b.y; acc[3][2] += a.w * b.z; acc[3][3] += a.w * b.w;
        }
        __syncthreads();
    }

    #pragma unroll
    for (int i = 0; i < 4; i++) {
        const int m = bm + tm + i;
        #pragma unroll
        for (int j = 0; j < 4; j++) {
            const int nn = bn + tn + j;
            float v = acc[i][j];
            if (bias) v += bias[nn];
            if (act == 1) {
                v = (v >= 0.f) ? v : 0.01f * v;
            } else if (act == 2) {
                float den = rnorm[m] * cnorm[nn];
                v = (den != 0.f) ? v / den : 0.f;
            }
            C[(size_t)m * N + nn] = v;
        }
    }
}

// ---------------- GRU gate kernels ----------------
__device__ __forceinline__ float sigmoidf_(float x) { return 1.f / (1.f + expf(-x)); }

// Layer 0: xW computed inline (K=6). Writes new h and hs[:,t,:].
__global__ void gru_gate0(const float* __restrict__ inp, const float* __restrict__ W_ih,
                          const float* __restrict__ b_ih, int t)
{
    const int n = blockIdx.x;
    const int j = threadIdx.x;          // 0..255
    __shared__ float xs[DF];
    if (j < DF) xs[j] = inp[n * (DF * TT) + j * TT + t];
    __syncthreads();

    float xw[3];
    #pragma unroll
    for (int gi = 0; gi < 3; gi++) {
        const int g = gi * HID + j;
        float v = b_ih[g];
        #pragma unroll
        for (int f = 0; f < DF; f++) v += xs[f] * W_ih[g * DF + f];
        xw[gi] = v;
    }
    const float hr = g_gh[n * G3 + j];
    const float hz = g_gh[n * G3 + HID + j];
    const float hn = g_gh[n * G3 + 2 * HID + j];
    const float h  = g_h[n * HID + j];
    const float r  = sigmoidf_(xw[0] + hr);
    const float z  = sigmoidf_(xw[1] + hz);
    const float nn = tanhf(xw[2] + r * hn);
    const float hnew = (1.f - z) * nn + z * h;
    g_h[n * HID + j] = hnew;
    g_hs[(n * TT + t) * HID + j] = hnew;
}

// Layer 1: xW read from precomputed g_xw1. Only updates h.
__global__ void gru_gate1(int t)
{
    const int n = blockIdx.x;
    const int j = threadIdx.x;
    const size_t xrow = ((size_t)n * TT + t) * G3;
    const float xr = g_xw1[xrow + j];
    const float xz = g_xw1[xrow + HID + j];
    const float xn = g_xw1[xrow + 2 * HID + j];
    const float hr = g_gh[n * G3 + j];
    const float hz = g_gh[n * G3 + HID + j];
    const float hn = g_gh[n * G3 + 2 * HID + j];
    const float h  = g_h[n * HID + j];
    const float r  = sigmoidf_(xr + hr);
    const float z  = sigmoidf_(xz + hz);
    const float nn = tanhf(xn + r * hn);
    g_h[n * HID + j] = (1.f - z) * nn + z * h;
}

// ---------------- small kernels ----------------
__global__ void mb_day_mean()
{
    const int b = blockIdx.x, h = threadIdx.x;
    float s = 0.f;
    for (int st = 0; st < 512; st++) s += g_mb[(b * 512 + st) * HID + h];
    g_mbday[b * HID + h] = s * (1.f / 512.f);
}

__global__ void day_topk(const float* __restrict__ thd /* 240 x 256 */)
{
    const int b = blockIdx.x;
    const int d = threadIdx.x;
    __shared__ float sim[NDAYS];
    const float* mbd = g_mbday + b * HID;
    float xn = 0.f;
    for (int i = 0; i < HID; i++) { float v = mbd[i]; xn += v * v; }
    xn = sqrtf(xn);
    if (d < NDAYS) {
        const float* yr = thd + d * HID;
        float yn = 0.f, dot = 0.f;
        for (int i = 0; i < HID; i++) { float y = yr[i]; yn += y * y; dot += mbd[i] * y; }
        const float den = xn * sqrtf(yn);
        sim[d] = (den != 0.f) ? dot / den : 0.f;
    }
    __syncthreads();
    if (d == 0) {
        for (int kk = 0; kk < KDAY; kk++) {
            float best = -1e30f; int bi = 0;
            for (int q = 0; q < NDAYS; q++)
                if (sim[q] > best) { best = sim[q]; bi = q; }
            g_dayidx[b * KDAY + kk] = bi;
            sim[bi] = -1e30f;
        }
    }
}

__global__ void make_rowmap()
{
    const int m = blockIdx.x * 256 + threadIdx.x;
    if (m < NSAMP) g_rowmap[m] = g_dayidx[m >> 9] * 512 + (m & 511);
}

__global__ void rownorm256(const float* __restrict__ X, float* __restrict__ out, int R)
{
    const int warp = (blockIdx.x * blockDim.x + threadIdx.x) >> 5;
    const int lane = threadIdx.x & 31;
    if (warp >= R) return;
    const float* r = X + (size_t)warp * HID;
    float s = 0.f;
    for (int i = lane; i < HID; i += 32) { float v = r[i]; s += v * v; }
    #pragma unroll
    for (int o = 16; o > 0; o >>= 1) s += __shfl_xor_sync(0xffffffffu, s, o);
    if (lane == 0) out[warp] = sqrtf(s);
}

// per-query top-10 over the 20480-wide cs row
__global__ void neigh_topk()
{
    const int n = blockIdx.x;
    const int tid = threadIdx.x;   // 256
    const float* row = g_cs + (size_t)n * NSAMP;

    float tv[NNB]; int ti[NNB];
    #pragma unroll
    for (int i = 0; i < NNB; i++) { tv[i] = -1e30f; ti[i] = 0x7fffffff; }

    for (int it = 0; it < NSAMP / 256; it++) {
        const int idx = tid + it * 256;
        const float v = row[idx];
        if (v > tv[NNB - 1]) {
            int p = NNB - 1;
            while (p > 0 && tv[p - 1] < v) { tv[p] = tv[p - 1]; ti[p] = ti[p - 1]; p--; }
            tv[p] = v; ti[p] = idx;
        }
    }

    __shared__ float sval[256 * NNB];
    __shared__ int   sidx[256 * NNB];
    __shared__ float rv[256];
    __shared__ int   rp[256];
    #pragma unroll
    for (int i = 0; i < NNB; i++) { sval[tid * NNB + i] = tv[i]; sidx[tid * NNB + i] = ti[i]; }
    __syncthreads();

    for (int kk = 0; kk < NNB; kk++) {
        float best = -1e30f; int bp = tid * NNB;
        #pragma unroll
        for (int i = 0; i < NNB; i++) {
            const float v = sval[tid * NNB + i];
            if (v > best) { best = v; bp = tid * NNB + i; }
        }
        rv[tid] = best; rp[tid] = bp;
        __syncthreads();
        for (int s = 128; s > 0; s >>= 1) {
            if (tid < s && rv[tid + s] > rv[tid]) { rv[tid] = rv[tid + s]; rp[tid] = rp[tid + s]; }
            __syncthreads();
        }
        if (tid == 0) {
            const int p = rp[0];
            g_vals[n * NNB + kk] = rv[0];
            g_nidx[n * NNB + kk] = sidx[p];
            sval[p] = -1e30f;
        }
        __syncthreads();
    }
}

__global__ void agg_fc(const float* __restrict__ fc_W, const float* __restrict__ fc_b,
                       float* __restrict__ y)
{
    const int n = blockIdx.x, h = threadIdx.x;
    float agg = 0.f;
    #pragma unroll
    for (int k = 0; k < NNB; k++) {
        const float v = g_vals[n * NNB + k] * (1.f / NNB);
        const int id = g_nidx[n * NNB + k];
        agg += v * g_kh[(size_t)id * HID + h];
    }
    float part = fc_W[h] * g_mb[n * HID + h] + fc_W[HID + h] * agg;
    __shared__ float red[256];
    red[h] = part;
    __syncthreads();
    for (int s = 128; s > 0; s >>= 1) {
        if (h < s) red[h] += red[h + s];
        __syncthreads();
    }
    if (h == 0) y[n] = red[0] + fc_b[0];
}

// ---------------- host ----------------
extern "C" void kernel_launch(void* const* d_in, const int* in_sizes, int n_in,
                              void* d_out, int out_size)
{
    const float* inp       = (const float*)d_in[0];
    const float* train_hid = (const float*)d_in[1];
    const float* thd       = (const float*)d_in[2];
    const float* W_ih0     = (const float*)d_in[3];
    const float* W_hh0     = (const float*)d_in[4];
    const float* b_ih0     = (const float*)d_in[5];
    const float* b_hh0     = (const float*)d_in[6];
    const float* W_ih1     = (const float*)d_in[7];
    const float* W_hh1     = (const float*)d_in[8];
    const float* b_ih1     = (const float*)d_in[9];
    const float* b_hh1     = (const float*)d_in[10];
    const float* lin0_W    = (const float*)d_in[11];
    const float* lin0_b    = (const float*)d_in[12];
    const float* lin1_W    = (const float*)d_in[13];
    const float* lin1_b    = (const float*)d_in[14];
    const float* lin2_W    = (const float*)d_in[15];
    const float* lin2_b    = (const float*)d_in[16];
    const float* proj1_W   = (const float*)d_in[17];
    const float* proj2_W   = (const float*)d_in[18];
    const float* fc_W      = (const float*)d_in[19];
    const float* fc_b      = (const float*)d_in[20];
    (void)in_sizes; (void)n_in; (void)out_size;

    float *p_h, *p_gh, *p_hs, *p_xw1, *p_mb1, *p_mb2, *p_mb, *p_kh, *p_khn, *p_q, *p_qn, *p_cs;
    int *p_rowmap;
    cudaGetSymbolAddress((void**)&p_h, g_h);
    cudaGetSymbolAddress((void**)&p_gh, g_gh);
    cudaGetSymbolAddress((void**)&p_hs, g_hs);
    cudaGetSymbolAddress((void**)&p_xw1, g_xw1);
    cudaGetSymbolAddress((void**)&p_mb1, g_mb1);
    cudaGetSymbolAddress((void**)&p_mb2, g_mb2);
    cudaGetSymbolAddress((void**)&p_mb, g_mb);
    cudaGetSymbolAddress((void**)&p_kh, g_kh);
    cudaGetSymbolAddress((void**)&p_khn, g_khn);
    cudaGetSymbolAddress((void**)&p_q, g_q);
    cudaGetSymbolAddress((void**)&p_qn, g_qn);
    cudaGetSymbolAddress((void**)&p_cs, g_cs);
    cudaGetSymbolAddress((void**)&p_rowmap, g_rowmap);

    // ---- GRU layer 0 ----
    cudaMemsetAsync(p_h, 0, BSZ * HID * sizeof(float));
    for (int t = 0; t < TT; t++) {
        gemm_tn<<<dim3(G3 / BN, BSZ / BM), 256>>>(p_h, W_hh0, b_hh0, p_gh,
                                                  BSZ, G3, HID, 0, nullptr, nullptr, nullptr);
        gru_gate0<<<BSZ, HID>>>(inp, W_ih0, b_ih0, t);
    }

    // ---- layer-1 input gates (one big GEMM) ----
    gemm_tn<<<dim3(G3 / BN, (BSZ * TT) / BM), 256>>>(p_hs, W_ih1, b_ih1, p_xw1,
                                                     BSZ * TT, G3, HID, 0, nullptr, nullptr, nullptr);

    // ---- GRU layer 1 ----
    cudaMemsetAsync(p_h, 0, BSZ * HID * sizeof(float));
    for (int t = 0; t < TT; t++) {
        gemm_tn<<<dim3(G3 / BN, BSZ / BM), 256>>>(p_h, W_hh1, b_hh1, p_gh,
                                                  BSZ, G3, HID, 0, nullptr, nullptr, nullptr);
        gru_gate1<<<BSZ, HID>>>(t);
    }

    // ---- MLP (leaky relu) ----
    gemm_tn<<<dim3(512 / BN, BSZ / BM), 256>>>(p_h, lin0_W, lin0_b, p_mb1,
                                               BSZ, 512, HID, 1, nullptr, nullptr, nullptr);
    gemm_tn<<<dim3(512 / BN, BSZ / BM), 256>>>(p_mb1, lin1_W, lin1_b, p_mb2,
                                               BSZ, 512, 512, 1, nullptr, nullptr, nullptr);
    gemm_tn<<<dim3(HID / BN, BSZ / BM), 256>>>(p_mb2, lin2_W, lin2_b, p_mb,
                                               BSZ, HID, 512, 1, nullptr, nullptr, nullptr);

    // ---- day similarity + gather ----
    mb_day_mean<<<4, HID>>>();
    day_topk<<<4, 256>>>(thd);
    make_rowmap<<<NSAMP / 256, 256>>>();
    gemm_tn<<<dim3(HID / BN, NSAMP / BM), 256>>>(train_hid, proj2_W, nullptr, p_kh,
                                                 NSAMP, HID, HID, 0, p_rowmap, nullptr, nullptr);
    rownorm256<<<(NSAMP * 32) / 256, 256>>>(p_kh, p_khn, NSAMP);

    // ---- queries + cosine sim + neighbor aggregation ----
    gemm_tn<<<dim3(HID / BN, BSZ / BM), 256>>>(p_mb, proj1_W, nullptr, p_q,
                                               BSZ, HID, HID, 0, nullptr, nullptr, nullptr);
    rownorm256<<<(BSZ * 32) / 256, 256>>>(p_q, p_qn, BSZ);
    gemm_tn<<<dim3(NSAMP / BN, BSZ / BM), 256>>>(p_q, p_kh, nullptr, p_cs,
                                                 BSZ, NSAMP, HID, 2, nullptr, p_qn, p_khn);
    neigh_topk<<<BSZ, 256>>>();
    agg_fc<<<BSZ, 256>>>(fc_W, fc_b, (float*)d_out);
}

// round 5
// speedup vs baseline: 1.1696x; 1.1696x over previous
#include <cuda_runtime.h>
#include <cmath>
#include <cstdint>

#define BSZ   2048          // B_DAYS * STOCKS
#define TT    60
#define HID   256
#define G3    768           // 3*HID
#define DF    6
#define NSAMP 20480         // 4 * K_DAY * STOCKS
#define NDAYS 240
#define KDAY  10
#define NNB   10

// ---------------- device scratch (no allocations allowed) ----------------
__device__ float g_h[BSZ * HID];
__device__ float g_hb[BSZ * HID];             // ping-pong partner of g_h
__device__ float g_hs[BSZ * TT * HID];        // layer-0 hidden sequence
__device__ float g_xw1[(size_t)BSZ * TT * G3];// layer-1 input gates
__device__ float g_mb1[BSZ * 512];
__device__ float g_mb2[BSZ * 512];
__device__ float g_mb[BSZ * HID];
__device__ float g_mbday[4 * HID];
__device__ int   g_dayidx[4 * KDAY];
__device__ int   g_rowmap[NSAMP];
__device__ float g_kh[NSAMP * HID];
__device__ float g_khn[NSAMP];
__device__ float g_q[BSZ * HID];
__device__ float g_qn[BSZ];
__device__ float g_cs[(size_t)BSZ * NSAMP];
__device__ float g_vals[BSZ * NNB];
__device__ int   g_nidx[BSZ * NNB];

// ---------------- generic fp32 GEMM: C[M,N] = A[M,K] @ B[N,K]^T ----------------
#define BM 64
#define BN 64
#define BK 16

__global__ void gemm_tn(const float* __restrict__ A, const float* __restrict__ B,
                        const float* __restrict__ bias, float* __restrict__ C,
                        int M, int N, int K, int act,
                        const int* __restrict__ rowmap,
                        const float* __restrict__ rnorm, const float* __restrict__ cnorm)
{
    __shared__ float As[BK][BM];
    __shared__ float Bs[BK][BN];
    const int bm = blockIdx.y * BM;
    const int bn = blockIdx.x * BN;
    const int tid = threadIdx.x;
    const int lr = tid >> 2;
    const int lc = (tid & 3) * 4;
    const int tm = (tid >> 4) * 4;
    const int tn = (tid & 15) * 4;

    int arow = bm + lr;
    if (rowmap) arow = rowmap[arow];
    const float* Ar = A + (size_t)arow * K;
    const float* Br = B + (size_t)(bn + lr) * K;

    float acc[4][4] = {};

    for (int k0 = 0; k0 < K; k0 += BK) {
        float4 av = *(const float4*)(Ar + k0 + lc);
        float4 bv = *(const float4*)(Br + k0 + lc);
        As[lc + 0][lr] = av.x; As[lc + 1][lr] = av.y;
        As[lc + 2][lr] = av.z; As[lc + 3][lr] = av.w;
        Bs[lc + 0][lr] = bv.x; Bs[lc + 1][lr] = bv.y;
        Bs[lc + 2][lr] = bv.z; Bs[lc + 3][lr] = bv.w;
        __syncthreads();
        #pragma unroll
        for (int kk = 0; kk < BK; kk++) {
            float4 a = *(const float4*)&As[kk][tm];
            float4 b = *(const float4*)&Bs[kk][tn];
            acc[0][0] += a.x * b.x; acc[0][1] += a.x * b.y; acc[0][2] += a.x * b.z; acc[0][3] += a.x * b.w;
            acc[1][0] += a.y * b.x; acc[1][1] += a.y * b.y; acc[1][2] += a.y * b.z; acc[1][3] += a.y * b.w;
            acc[2][0] += a.z * b.x; acc[2][1] += a.z * b.y; acc[2][2] += a.z * b.z; acc[2][3] += a.z * b.w;
            acc[3][0] += a.w * b.x; acc[3][1] += a.w * b.y; acc[3][2] += a.w * b.z; acc[3][3] += a.w * b.w;
        }
        __syncthreads();
    }

    #pragma unroll
    for (int i = 0; i < 4; i++) {
        const int m = bm + tm + i;
        #pragma unroll
        for (int j = 0; j < 4; j++) {
            const int nn = bn + tn + j;
            float v = acc[i][j];
            if (bias) v += bias[nn];
            if (act == 1) {
                v = (v >= 0.f) ? v : 0.01f * v;
            } else if (act == 2) {
                float den = rnorm[m] * cnorm[nn];
                v = (den != 0.f) ? v / den : 0.f;
            }
            C[(size_t)m * N + nn] = v;
        }
    }
}

// ---------------- 3xTF32 tensor-core GEMM: C[M,N] = A[M,K] @ B[N,K]^T + bias ----
// fp32-comparable accuracy via hi/lo split (a_hi*b_hi + a_hi*b_lo + a_lo*b_hi)
#define XBM 128
#define XBN 64
#define XBK 32
#define XPAD 36

__device__ __forceinline__ void split_tf32(float x, uint32_t& hi, uint32_t& lo)
{
    uint32_t h;
    asm("cvt.rna.tf32.f32 %0, %1;" : "=r"(h) : "f"(x));
    float rem = x - __uint_as_float(h);
    uint32_t l;
    asm("cvt.rna.tf32.f32 %0, %1;" : "=r"(l) : "f"(rem));
    hi = h; lo = l;
}

__device__ __forceinline__ void mma_tf32(float* d, const uint32_t* a, const uint32_t* b)
{
    asm volatile(
        "mma.sync.aligned.m16n8k8.row.col.f32.tf32.tf32.f32 "
        "{%0,%1,%2,%3}, {%4,%5,%6,%7}, {%8,%9}, {%0,%1,%2,%3};"
        : "+f"(d[0]), "+f"(d[1]), "+f"(d[2]), "+f"(d[3])
        : "r"(a[0]), "r"(a[1]), "r"(a[2]), "r"(a[3]), "r"(b[0]), "r"(b[1]));
}

__global__ void gemm_3xtf32(const float* __restrict__ A, const float* __restrict__ B,
                            const float* __restrict__ bias, float* __restrict__ C,
                            int M, int N, int K)
{
    __shared__ float As[XBM][XPAD];   // [m][k]
    __shared__ float Bs[XBN][XPAD];   // [n][k]
    const int bm = blockIdx.y * XBM;
    const int bn = blockIdx.x * XBN;
    const int tid = threadIdx.x;                 // 256
    const int warp = tid >> 5, lane = tid & 31;
    const int wm = (warp & 3) * 32;
    const int wn = (warp >> 2) * 32;
    const int g = lane >> 2, tg = lane & 3;

    float acc[2][4][4];
    #pragma unroll
    for (int a = 0; a < 2; a++)
        #pragma unroll
        for (int b = 0; b < 4; b++)
            #pragma unroll
            for (int c = 0; c < 4; c++) acc[a][b][c] = 0.f;

    for (int k0 = 0; k0 < K; k0 += XBK) {
        #pragma unroll
        for (int i = 0; i < 4; i++) {
            int idx = tid + i * 256;                   // 0..1023
            int r = idx >> 3, c4 = (idx & 7) * 4;
            float4 v = *(const float4*)(A + (size_t)(bm + r) * K + k0 + c4);
            As[r][c4 + 0] = v.x; As[r][c4 + 1] = v.y;
            As[r][c4 + 2] = v.z; As[r][c4 + 3] = v.w;
        }
        #pragma unroll
        for (int i = 0; i < 2; i++) {
            int idx = tid + i * 256;                   // 0..511
            int r = idx >> 3, c4 = (idx & 7) * 4;
            float4 v = *(const float4*)(B + (size_t)(bn + r) * K + k0 + c4);
            Bs[r][c4 + 0] = v.x; Bs[r][c4 + 1] = v.y;
            Bs[r][c4 + 2] = v.z; Bs[r][c4 + 3] = v.w;
        }
        __syncthreads();
        #pragma unroll
        for (int kc = 0; kc < 4; kc++) {
            const int kb = kc * 8;
            uint32_t ahi[2][4], alo[2][4];
            #pragma unroll
            for (int mt = 0; mt < 2; mt++) {
                const int r0 = wm + mt * 16;
                split_tf32(As[r0 + g][kb + tg],         ahi[mt][0], alo[mt][0]);
                split_tf32(As[r0 + g + 8][kb + tg],     ahi[mt][1], alo[mt][1]);
                split_tf32(As[r0 + g][kb + tg + 4],     ahi[mt][2], alo[mt][2]);
                split_tf32(As[r0 + g + 8][kb + tg + 4], ahi[mt][3], alo[mt][3]);
            }
            uint32_t bhi[4][2], blo[4][2];
            #pragma unroll
            for (int nt = 0; nt < 4; nt++) {
                const int c0 = wn + nt * 8;
                split_tf32(Bs[c0 + g][kb + tg],     bhi[nt][0], blo[nt][0]);
                split_tf32(Bs[c0 + g][kb + tg + 4], bhi[nt][1], blo[nt][1]);
            }
            #pragma unroll
            for (int mt = 0; mt < 2; mt++)
                #pragma unroll
                for (int nt = 0; nt < 4; nt++) {
                    mma_tf32(acc[mt][nt], alo[mt], bhi[nt]);
                    mma_tf32(acc[mt][nt], ahi[mt], blo[nt]);
                    mma_tf32(acc[mt][nt], ahi[mt], bhi[nt]);
                }
        }
        __syncthreads();
    }

    #pragma unroll
    for (int mt = 0; mt < 2; mt++) {
        #pragma unroll
        for (int nt = 0; nt < 4; nt++) {
            const int r0 = bm + wm + mt * 16 + g;
            const int c0 = bn + wn + nt * 8 + tg * 2;
            const float bi0 = bias ? bias[c0] : 0.f;
            const float bi1 = bias ? bias[c0 + 1] : 0.f;
            C[(size_t)r0 * N + c0]           = acc[mt][nt][0] + bi0;
            C[(size_t)r0 * N + c0 + 1]       = acc[mt][nt][1] + bi1;
            C[(size_t)(r0 + 8) * N + c0]     = acc[mt][nt][2] + bi0;
            C[(size_t)(r0 + 8) * N + c0 + 1] = acc[mt][nt][3] + bi1;
        }
    }
}

// ---------------- fused GRU step kernels ----------------
__device__ __forceinline__ float sigmoidf_(float x) { return 1.f / (1.f + expf(-x)); }

// One GRU step, layer 0. grid = dim3(4, 32). Each CTA: 64 rows x 64 gate-cols
// of all three gate groups. Fused gate epilogue; writes hout and g_hs[:,t,:].
__global__ void gru_step0(const float* __restrict__ hin, float* __restrict__ hout,
                          const float* __restrict__ Whh, const float* __restrict__ bhh,
                          const float* __restrict__ inp, const float* __restrict__ Wih,
                          const float* __restrict__ bih, int t)
{
    __shared__ float As[BK][BM];
    __shared__ float Bs[3][BK][BM];
    __shared__ float wih_s[BM][3 * DF];
    __shared__ float bih_s[3][BM];
    __shared__ float bhh_s[3][BM];
    __shared__ float xs[BM][DF];

    const int bm = blockIdx.y * BM;
    const int bn = blockIdx.x * BM;   // gate-col base within [0,256)
    const int tid = threadIdx.x;
    const int lr = tid >> 2, lc = (tid & 3) * 4;
    const int tm = (tid >> 4) * 4, tn = (tid & 15) * 4;

    for (int idx = tid; idx < BM * 3 * DF; idx += 256) {
        const int c = idx / (3 * DF), rem = idx % (3 * DF);
        const int gg = rem / DF, f = rem % DF;
        wih_s[c][gg * DF + f] = Wih[(gg * HID + bn + c) * DF + f];
    }
    for (int idx = tid; idx < 3 * BM; idx += 256) {
        const int gg = idx / BM, c = idx % BM;
        bih_s[gg][c] = bih[gg * HID + bn + c];
        bhh_s[gg][c] = bhh[gg * HID + bn + c];
    }
    for (int idx = tid; idx < BM * DF; idx += 256) {
        const int r = idx / DF, f = idx % DF;
        xs[r][f] = inp[(bm + r) * (DF * TT) + f * TT + t];
    }

    float aR[4][4] = {}, aZ[4][4] = {}, aN[4][4] = {};
    const float* Arow = hin + (size_t)(bm + lr) * HID;

    for (int k0 = 0; k0 < HID; k0 += BK) {
        float4 av = *(const float4*)(Arow + k0 + lc);
        As[lc + 0][lr] = av.x; As[lc + 1][lr] = av.y;
        As[lc + 2][lr] = av.z; As[lc + 3][lr] = av.w;
        #pragma unroll
        for (int gg = 0; gg < 3; gg++) {
            float4 bv = *(const float4*)(Whh + (size_t)(gg * HID + bn + lr) * HID + k0 + lc);
            Bs[gg][lc + 0][lr] = bv.x; Bs[gg][lc + 1][lr] = bv.y;
            Bs[gg][lc + 2][lr] = bv.z; Bs[gg][lc + 3][lr] = bv.w;
        }
        __syncthreads();
        #pragma unroll
        for (int kk = 0; kk < BK; kk++) {
            float4 a  = *(const float4*)&As[kk][tm];
            float4 bR = *(const float4*)&Bs[0][kk][tn];
            float4 bZ = *(const float4*)&Bs[1][kk][tn];
            float4 bN = *(const float4*)&Bs[2][kk][tn];
            aR[0][0] += a.x * bR.x; aR[0][1] += a.x * bR.y; aR[0][2] += a.x * bR.z; aR[0][3] += a.x * bR.w;
            aR[1][0] += a.y * bR.x; aR[1][1] += a.y * bR.y; aR[1][2] += a.y * bR.z; aR[1][3] += a.y * bR.w;
            aR[2][0] += a.z * bR.x; aR[2][1] += a.z * bR.y; aR[2][2] += a.z * bR.z; aR[2][3] += a.z * bR.w;
            aR[3][0] += a.w * bR.x; aR[3][1] += a.w * bR.y; aR[3][2] += a.w * bR.z; aR[3][3] += a.w * bR.w;
            aZ[0][0] += a.x * bZ.x; aZ[0][1] += a.x * bZ.y; aZ[0][2] += a.x * bZ.z; aZ[0][3] += a.x * bZ.w;
            aZ[1][0] += a.y * bZ.x; aZ[1][1] += a.y * bZ.y; aZ[1][2] += a.y * bZ.z; aZ[1][3] += a.y * bZ.w;
            aZ[2][0] += a.z * bZ.x; aZ[2][1] += a.z * bZ.y; aZ[2][2] += a.z * bZ.z; aZ[2][3] += a.z * bZ.w;
            aZ[3][0] += a.w * bZ.x; aZ[3][1] += a.w * bZ.y; aZ[3][2] += a.w * bZ.z; aZ[3][3] += a.w * bZ.w;
            aN[0][0] += a.x * bN.x; aN[0][1] += a.x * bN.y; aN[0][2] += a.x * bN.z; aN[0][3] += a.x * bN.w;
            aN[1][0] += a.y * bN.x; aN[1][1] += a.y * bN.y; aN[1][2] += a.y * bN.z; aN[1][3] += a.y * bN.w;
            aN[2][0] += a.z * bN.x; aN[2][1] += a.z * bN.y; aN[2][2] += a.z * bN.z; aN[2][3] += a.z * bN.w;
            aN[3][0] += a.w * bN.x; aN[3][1] += a.w * bN.y; aN[3][2] += a.w * bN.z; aN[3][3] += a.w * bN.w;
        }
        __syncthreads();
    }

    #pragma unroll
    for (int i = 0; i < 4; i++) {
        const int rl = tm + i, row = bm + rl;
        #pragma unroll
        for (int j = 0; j < 4; j++) {
            const int cl = tn + j, gc = bn + cl;
            float xr = bih_s[0][cl], xz = bih_s[1][cl], xn = bih_s[2][cl];
            #pragma unroll
            for (int f = 0; f < DF; f++) {
                const float xv = xs[rl][f];
                xr += xv * wih_s[cl][0 * DF + f];
                xz += xv * wih_s[cl][1 * DF + f];
                xn += xv * wih_s[cl][2 * DF + f];
            }
            const float r  = sigmoidf_(xr + aR[i][j] + bhh_s[0][cl]);
            const float z  = sigmoidf_(xz + aZ[i][j] + bhh_s[1][cl]);
            const float nn = tanhf(xn + r * (aN[i][j] + bhh_s[2][cl]));
            const float ho = hin[(size_t)row * HID + gc];
            const float hv = (1.f - z) * nn + z * ho;
            hout[(size_t)row * HID + gc] = hv;
            g_hs[((size_t)row * TT + t) * HID + gc] = hv;
        }
    }
}

// One GRU step, layer 1. xw read from g_xw1.
__global__ void gru_step1(const float* __restrict__ hin, float* __restrict__ hout,
                          const float* __restrict__ Whh, const float* __restrict__ bhh, int t)
{
    __shared__ float As[BK][BM];
    __shared__ float Bs[3][BK][BM];
    __shared__ float bhh_s[3][BM];

    const int bm = blockIdx.y * BM;
    const int bn = blockIdx.x * BM;
    const int tid = threadIdx.x;
    const int lr = tid >> 2, lc = (tid & 3) * 4;
    const int tm = (tid >> 4) * 4, tn = (tid & 15) * 4;

    for (int idx = tid; idx < 3 * BM; idx += 256) {
        const int gg = idx / BM, c = idx % BM;
        bhh_s[gg][c] = bhh[gg * HID + bn + c];
    }

    float aR[4][4] = {}, aZ[4][4] = {}, aN[4][4] = {};
    const float* Arow = hin + (size_t)(bm + lr) * HID;

    for (int k0 = 0; k0 < HID; k0 += BK) {
        float4 av = *(const float4*)(Arow + k0 + lc);
        As[lc + 0][lr] = av.x; As[lc + 1][lr] = av.y;
        As[lc + 2][lr] = av.z; As[lc + 3][lr] = av.w;
        #pragma unroll
        for (int gg = 0; gg < 3; gg++) {
            float4 bv = *(const float4*)(Whh + (size_t)(gg * HID + bn + lr) * HID + k0 + lc);
            Bs[gg][lc + 0][lr] = bv.x; Bs[gg][lc + 1][lr] = bv.y;
            Bs[gg][lc + 2][lr] = bv.z; Bs[gg][lc + 3][lr] = bv.w;
        }
        __syncthreads();
        #pragma unroll
        for (int kk = 0; kk < BK; kk++) {
            float4 a  = *(const float4*)&As[kk][tm];
            float4 bR = *(const float4*)&Bs[0][kk][tn];
            float4 bZ = *(const float4*)&Bs[1][kk][tn];
            float4 bN = *(const float4*)&Bs[2][kk][tn];
            aR[0][0] += a.x * bR.x; aR[0][1] += a.x * bR.y; aR[0][2] += a.x * bR.z; aR[0][3] += a.x * bR.w;
            aR[1][0] += a.y * bR.x; aR[1][1] += a.y * bR.y; aR[1][2] += a.y * bR.z; aR[1][3] += a.y * bR.w;
            aR[2][0] += a.z * bR.x; aR[2][1] += a.z * bR.y; aR[2][2] += a.z * bR.z; aR[2][3] += a.z * bR.w;
            aR[3][0] += a.w * bR.x; aR[3][1] += a.w * bR.y; aR[3][2] += a.w * bR.z; aR[3][3] += a.w * bR.w;
            aZ[0][0] += a.x * bZ.x; aZ[0][1] += a.x * bZ.y; aZ[0][2] += a.x * bZ.z; aZ[0][3] += a.x * bZ.w;
            aZ[1][0] += a.y * bZ.x; aZ[1][1] += a.y * bZ.y; aZ[1][2] += a.y * bZ.z; aZ[1][3] += a.y * bZ.w;
            aZ[2][0] += a.z * bZ.x; aZ[2][1] += a.z * bZ.y; aZ[2][2] += a.z * bZ.z; aZ[2][3] += a.z * bZ.w;
            aZ[3][0] += a.w * bZ.x; aZ[3][1] += a.w * bZ.y; aZ[3][2] += a.w * bZ.z; aZ[3][3] += a.w * bZ.w;
            aN[0][0] += a.x * bN.x; aN[0][1] += a.x * bN.y; aN[0][2] += a.x * bN.z; aN[0][3] += a.x * bN.w;
            aN[1][0] += a.y * bN.x; aN[1][1] += a.y * bN.y; aN[1][2] += a.y * bN.z; aN[1][3] += a.y * bN.w;
            aN[2][0] += a.z * bN.x; aN[2][1] += a.z * bN.y; aN[2][2] += a.z * bN.z; aN[2][3] += a.z * bN.w;
            aN[3][0] += a.w * bN.x; aN[3][1] += a.w * bN.y; aN[3][2] += a.w * bN.z; aN[3][3] += a.w * bN.w;
        }
        __syncthreads();
    }

    #pragma unroll
    for (int i = 0; i < 4; i++) {
        const int row = bm + tm + i;
        const size_t xb = ((size_t)row * TT + t) * G3 + bn + tn;
        float4 xr4 = *(const float4*)(g_xw1 + xb);
        float4 xz4 = *(const float4*)(g_xw1 + xb + HID);
        float4 xn4 = *(const float4*)(g_xw1 + xb + 2 * HID);
        const float* xr = (const float*)&xr4;
        const float* xz = (const float*)&xz4;
        const float* xn = (const float*)&xn4;
        #pragma unroll
        for (int j = 0; j < 4; j++) {
            const int cl = tn + j, gc = bn + cl;
            const float r  = sigmoidf_(xr[j] + aR[i][j] + bhh_s[0][cl]);
            const float z  = sigmoidf_(xz[j] + aZ[i][j] + bhh_s[1][cl]);
            const float nn = tanhf(xn[j] + r * (aN[i][j] + bhh_s[2][cl]));
            const float ho = hin[(size_t)row * HID + gc];
            hout[(size_t)row * HID + gc] = (1.f - z) * nn + z * ho;
        }
    }
}

// ---------------- small kernels ----------------
__global__ void mb_day_mean()
{
    const int b = blockIdx.x, h = threadIdx.x;
    float s = 0.f;
    for (int st = 0; st < 512; st++) s += g_mb[(b * 512 + st) * HID + h];
    g_mbday[b * HID + h] = s * (1.f / 512.f);
}

__global__ void day_topk(const float* __restrict__ thd)
{
    const int b = blockIdx.x;
    const int d = threadIdx.x;
    __shared__ float sim[NDAYS];
    const float* mbd = g_mbday + b * HID;
    float xn = 0.f;
    for (int i = 0; i < HID; i++) { float v = mbd[i]; xn += v * v; }
    xn = sqrtf(xn);
    if (d < NDAYS) {
        const float* yr = thd + d * HID;
        float yn = 0.f, dot = 0.f;
        for (int i = 0; i < HID; i++) { float y = yr[i]; yn += y * y; dot += mbd[i] * y; }
        const float den = xn * sqrtf(yn);
        sim[d] = (den != 0.f) ? dot / den : 0.f;
    }
    __syncthreads();
    if (d == 0) {
        for (int kk = 0; kk < KDAY; kk++) {
            float best = -1e30f; int bi = 0;
            for (int q = 0; q < NDAYS; q++)
                if (sim[q] > best) { best = sim[q]; bi = q; }
            g_dayidx[b * KDAY + kk] = bi;
            sim[bi] = -1e30f;
        }
    }
}

__global__ void make_rowmap()
{
    const int m = blockIdx.x * 256 + threadIdx.x;
    if (m < NSAMP) g_rowmap[m] = g_dayidx[m >> 9] * 512 + (m & 511);
}

__global__ void rownorm256(const float* __restrict__ X, float* __restrict__ out, int R)
{
    const int warp = (blockIdx.x * blockDim.x + threadIdx.x) >> 5;
    const int lane = threadIdx.x & 31;
    if (warp >= R) return;
    const float* r = X + (size_t)warp * HID;
    float s = 0.f;
    for (int i = lane; i < HID; i += 32) { float v = r[i]; s += v * v; }
    #pragma unroll
    for (int o = 16; o > 0; o >>= 1) s += __shfl_xor_sync(0xffffffffu, s, o);
    if (lane == 0) out[warp] = sqrtf(s);
}

__global__ void neigh_topk()
{
    const int n = blockIdx.x;
    const int tid = threadIdx.x;
    const float* row = g_cs + (size_t)n * NSAMP;

    float tv[NNB]; int ti[NNB];
    #pragma unroll
    for (int i = 0; i < NNB; i++) { tv[i] = -1e30f; ti[i] = 0x7fffffff; }

    for (int it = 0; it < NSAMP / 256; it++) {
        const int idx = tid + it * 256;
        const float v = row[idx];
        if (v > tv[NNB - 1]) {
            int p = NNB - 1;
            while (p > 0 && tv[p - 1] < v) { tv[p] = tv[p - 1]; ti[p] = ti[p - 1]; p--; }
            tv[p] = v; ti[p] = idx;
        }
    }

    __shared__ float sval[256 * NNB];
    __shared__ int   sidx[256 * NNB];
    __shared__ float rv[256];
    __shared__ int   rp[256];
    #pragma unroll
    for (int i = 0; i < NNB; i++) { sval[tid * NNB + i] = tv[i]; sidx[tid * NNB + i] = ti[i]; }
    __syncthreads();

    for (int kk = 0; kk < NNB; kk++) {
        float best = -1e30f; int bp = tid * NNB;
        #pragma unroll
        for (int i = 0; i < NNB; i++) {
            const float v = sval[tid * NNB + i];
            if (v > best) { best = v; bp = tid * NNB + i; }
        }
        rv[tid] = best; rp[tid] = bp;
        __syncthreads();
        for (int s = 128; s > 0; s >>= 1) {
            if (tid < s && rv[tid + s] > rv[tid]) { rv[tid] = rv[tid + s]; rp[tid] = rp[tid + s]; }
            __syncthreads();
        }
        if (tid == 0) {
            const int p = rp[0];
            g_vals[n * NNB + kk] = rv[0];
            g_nidx[n * NNB + kk] = sidx[p];
            sval[p] = -1e30f;
        }
        __syncthreads();
    }
}

__global__ void agg_fc(const float* __restrict__ fc_W, const float* __restrict__ fc_b,
                       float* __restrict__ y)
{
    const int n = blockIdx.x, h = threadIdx.x;
    float agg = 0.f;
    #pragma unroll
    for (int k = 0; k < NNB; k++) {
        const float v = g_vals[n * NNB + k] * (1.f / NNB);
        const int id = g_nidx[n * NNB + k];
        agg += v * g_kh[(size_t)id * HID + h];
    }
    float part = fc_W[h] * g_mb[n * HID + h] + fc_W[HID + h] * agg;
    __shared__ float red[256];
    red[h] = part;
    __syncthreads();
    for (int s = 128; s > 0; s >>= 1) {
        if (h < s) red[h] += red[h + s];
        __syncthreads();
    }
    if (h == 0) y[n] = red[0] + fc_b[0];
}

// ---------------- host ----------------
extern "C" void kernel_launch(void* const* d_in, const int* in_sizes, int n_in,
                              void* d_out, int out_size)
{
    const float* inp       = (const float*)d_in[0];
    const float* train_hid = (const float*)d_in[1];
    const float* thd       = (const float*)d_in[2];
    const float* W_ih0     = (const float*)d_in[3];
    const float* W_hh0     = (const float*)d_in[4];
    const float* b_ih0     = (const float*)d_in[5];
    const float* b_hh0     = (const float*)d_in[6];
    const float* W_ih1     = (const float*)d_in[7];
    const float* W_hh1     = (const float*)d_in[8];
    const float* b_ih1     = (const float*)d_in[9];
    const float* b_hh1     = (const float*)d_in[10];
    const float* lin0_W    = (const float*)d_in[11];
    const float* lin0_b    = (const float*)d_in[12];
    const float* lin1_W    = (const float*)d_in[13];
    const float* lin1_b    = (const float*)d_in[14];
    const float* lin2_W    = (const float*)d_in[15];
    const float* lin2_b    = (const float*)d_in[16];
    const float* proj1_W   = (const float*)d_in[17];
    const float* proj2_W   = (const float*)d_in[18];
    const float* fc_W      = (const float*)d_in[19];
    const float* fc_b      = (const float*)d_in[20];
    (void)in_sizes; (void)n_in; (void)out_size;

    float *p_h, *p_hb, *p_hs, *p_xw1, *p_mb1, *p_mb2, *p_mb, *p_kh, *p_khn, *p_q, *p_qn, *p_cs;
    int *p_rowmap;
    cudaGetSymbolAddress((void**)&p_h, g_h);
    cudaGetSymbolAddress((void**)&p_hb, g_hb);
    cudaGetSymbolAddress((void**)&p_hs, g_hs);
    cudaGetSymbolAddress((void**)&p_xw1, g_xw1);
    cudaGetSymbolAddress((void**)&p_mb1, g_mb1);
    cudaGetSymbolAddress((void**)&p_mb2, g_mb2);
    cudaGetSymbolAddress((void**)&p_mb, g_mb);
    cudaGetSymbolAddress((void**)&p_kh, g_kh);
    cudaGetSymbolAddress((void**)&p_khn, g_khn);
    cudaGetSymbolAddress((void**)&p_q, g_q);
    cudaGetSymbolAddress((void**)&p_qn, g_qn);
    cudaGetSymbolAddress((void**)&p_cs, g_cs);
    cudaGetSymbolAddress((void**)&p_rowmap, g_rowmap);

    const dim3 gru_grid(HID / BM, BSZ / BM);   // (4, 32)

    // ---- GRU layer 0 (fused gemm+gate, ping-pong h) ----
    cudaMemsetAsync(p_h, 0, BSZ * HID * sizeof(float));
    for (int t = 0; t < TT; t++) {
        const float* hi = (t & 1) ? p_hb : p_h;
        float*       ho = (t & 1) ? p_h  : p_hb;
        gru_step0<<<gru_grid, 256>>>(hi, ho, W_hh0, b_hh0, inp, W_ih0, b_ih0, t);
    }

    // ---- layer-1 input gates: one big 3xTF32 tensor-core GEMM ----
    gemm_3xtf32<<<dim3(G3 / XBN, (BSZ * TT) / XBM), 256>>>(p_hs, W_ih1, b_ih1, p_xw1,
                                                           BSZ * TT, G3, HID);

    // ---- GRU layer 1 ----
    cudaMemsetAsync(p_h, 0, BSZ * HID * sizeof(float));
    for (int t = 0; t < TT; t++) {
        const float* hi = (t & 1) ? p_hb : p_h;
        float*       ho = (t & 1) ? p_h  : p_hb;
        gru_step1<<<gru_grid, 256>>>(hi, ho, W_hh1, b_hh1, t);
    }
    // final h (t=59) is in g_h

    // ---- MLP (leaky relu) ----
    gemm_tn<<<dim3(512 / BN, BSZ / BM), 256>>>(p_h, lin0_W, lin0_b, p_mb1,
                                               BSZ, 512, HID, 1, nullptr, nullptr, nullptr);
    gemm_tn<<<dim3(512 / BN, BSZ / BM), 256>>>(p_mb1, lin1_W, lin1_b, p_mb2,
                                               BSZ, 512, 512, 1, nullptr, nullptr, nullptr);
    gemm_tn<<<dim3(HID / BN, BSZ / BM), 256>>>(p_mb2, lin2_W, lin2_b, p_mb,
                                               BSZ, HID, 512, 1, nullptr, nullptr, nullptr);

    // ---- day similarity + gather ----
    mb_day_mean<<<4, HID>>>();
    day_topk<<<4, 256>>>(thd);
    make_rowmap<<<NSAMP / 256, 256>>>();
    gemm_tn<<<dim3(HID / BN, NSAMP / BM), 256>>>(train_hid, proj2_W, nullptr, p_kh,
                                                 NSAMP, HID, HID, 0, p_rowmap, nullptr, nullptr);
    rownorm256<<<(NSAMP * 32) / 256, 256>>>(p_kh, p_khn, NSAMP);

    // ---- queries + cosine sim + neighbor aggregation ----
    gemm_tn<<<dim3(HID / BN, BSZ / BM), 256>>>(p_mb, proj1_W, nullptr, p_q,
                                               BSZ, HID, HID, 0, nullptr, nullptr, nullptr);
    rownorm256<<<(BSZ * 32) / 256, 256>>>(p_q, p_qn, BSZ);
    gemm_tn<<<dim3(NSAMP / BN, BSZ / BM), 256>>>(p_q, p_kh, nullptr, p_cs,
                                                 BSZ, NSAMP, HID, 2, nullptr, p_qn, p_khn);
    neigh_topk<<<BSZ, 256>>>();
    agg_fc<<<BSZ, 256>>>(fc_W, fc_b, (float*)d_out);
}

// round 6
// speedup vs baseline: 1.3621x; 1.1646x over previous
#include <cuda_runtime.h>
#include <cmath>
#include <cstdint>

#define BSZ   2048          // B_DAYS * STOCKS
#define TT    60
#define HID   256
#define G3    768           // 3*HID
#define DF    6
#define NSAMP 20480         // 4 * K_DAY * STOCKS
#define NDAYS 240
#define KDAY  10
#define NNB   10

// ---------------- device scratch (no allocations allowed) ----------------
__device__ float g_h[BSZ * HID];
__device__ float g_hb[BSZ * HID];             // ping-pong partner of g_h
__device__ float g_hs[BSZ * TT * HID];        // layer-0 hidden sequence
__device__ float g_xw1[(size_t)BSZ * TT * G3];// layer-1 input gates
__device__ float g_mb1[BSZ * 512];
__device__ float g_mb2[BSZ * 512];
__device__ float g_mb[BSZ * HID];
__device__ float g_mbday[4 * HID];
__device__ int   g_dayidx[4 * KDAY];
__device__ int   g_rowmap[NSAMP];
__device__ float g_kh[NSAMP * HID];
__device__ float g_khn[NSAMP];
__device__ float g_q[BSZ * HID];
__device__ float g_qn[BSZ];
__device__ float g_cs[(size_t)BSZ * NSAMP];
__device__ float g_vals[BSZ * NNB];
__device__ int   g_nidx[BSZ * NNB];

// ---------------- tf32 helpers ----------------
__device__ __forceinline__ void split_tf32(float x, uint32_t& hi, uint32_t& lo)
{
    uint32_t h;
    asm("cvt.rna.tf32.f32 %0, %1;" : "=r"(h) : "f"(x));
    float rem = x - __uint_as_float(h);
    uint32_t l;
    asm("cvt.rna.tf32.f32 %0, %1;" : "=r"(l) : "f"(rem));
    hi = h; lo = l;
}

__device__ __forceinline__ void mma_tf32(float* d, const uint32_t* a, const uint32_t* b)
{
    asm volatile(
        "mma.sync.aligned.m16n8k8.row.col.f32.tf32.tf32.f32 "
        "{%0,%1,%2,%3}, {%4,%5,%6,%7}, {%8,%9}, {%0,%1,%2,%3};"
        : "+f"(d[0]), "+f"(d[1]), "+f"(d[2]), "+f"(d[3])
        : "r"(a[0]), "r"(a[1]), "r"(a[2]), "r"(a[3]), "r"(b[0]), "r"(b[1]));
}

__device__ __forceinline__ float sigmoidf_(float x) { return 1.f / (1.f + expf(-x)); }

// ---------------- 3xTF32 tensor-core GEMM: C[M,N] = A[M,K] @ B[N,K]^T + bias ----
// act: 0 none, 1 leaky(0.01), 2 cosine-normalize by rnorm[m]*cnorm[n]
// rowmap: optional A-row gather. M%128==0, N%64==0, K%32==0.
#define XBM 128
#define XBN 64
#define XBK 32
#define XPAD 36

__global__ void gemm_x(const float* __restrict__ A, const float* __restrict__ B,
                       const float* __restrict__ bias, float* __restrict__ C,
                       int M, int N, int K, int act,
                       const int* __restrict__ rowmap,
                       const float* __restrict__ rnorm, const float* __restrict__ cnorm)
{
    __shared__ float As[XBM][XPAD];   // [m][k]
    __shared__ float Bs[XBN][XPAD];   // [n][k]
    const int bm = blockIdx.y * XBM;
    const int bn = blockIdx.x * XBN;
    const int tid = threadIdx.x;                 // 256
    const int warp = tid >> 5, lane = tid & 31;
    const int wm = (warp & 3) * 32;
    const int wn = (warp >> 2) * 32;
    const int g = lane >> 2, tg = lane & 3;

    float acc[2][4][4];
    #pragma unroll
    for (int a = 0; a < 2; a++)
        #pragma unroll
        for (int b = 0; b < 4; b++)
            #pragma unroll
            for (int c = 0; c < 4; c++) acc[a][b][c] = 0.f;

    for (int k0 = 0; k0 < K; k0 += XBK) {
        #pragma unroll
        for (int i = 0; i < 4; i++) {
            int idx = tid + i * 256;                   // 0..1023
            int r = idx >> 3, c4 = (idx & 7) * 4;
            int arow = bm + r;
            if (rowmap) arow = rowmap[arow];
            float4 v = *(const float4*)(A + (size_t)arow * K + k0 + c4);
            As[r][c4 + 0] = v.x; As[r][c4 + 1] = v.y;
            As[r][c4 + 2] = v.z; As[r][c4 + 3] = v.w;
        }
        #pragma unroll
        for (int i = 0; i < 2; i++) {
            int idx = tid + i * 256;                   // 0..511
            int r = idx >> 3, c4 = (idx & 7) * 4;
            float4 v = *(const float4*)(B + (size_t)(bn + r) * K + k0 + c4);
            Bs[r][c4 + 0] = v.x; Bs[r][c4 + 1] = v.y;
            Bs[r][c4 + 2] = v.z; Bs[r][c4 + 3] = v.w;
        }
        __syncthreads();
        #pragma unroll
        for (int kc = 0; kc < 4; kc++) {
            const int kb = kc * 8;
            uint32_t ahi[2][4], alo[2][4];
            #pragma unroll
            for (int mt = 0; mt < 2; mt++) {
                const int r0 = wm + mt * 16;
                split_tf32(As[r0 + g][kb + tg],         ahi[mt][0], alo[mt][0]);
                split_tf32(As[r0 + g + 8][kb + tg],     ahi[mt][1], alo[mt][1]);
                split_tf32(As[r0 + g][kb + tg + 4],     ahi[mt][2], alo[mt][2]);
                split_tf32(As[r0 + g + 8][kb + tg + 4], ahi[mt][3], alo[mt][3]);
            }
            uint32_t bhi[4][2], blo[4][2];
            #pragma unroll
            for (int nt = 0; nt < 4; nt++) {
                const int c0 = wn + nt * 8;
                split_tf32(Bs[c0 + g][kb + tg],     bhi[nt][0], blo[nt][0]);
                split_tf32(Bs[c0 + g][kb + tg + 4], bhi[nt][1], blo[nt][1]);
            }
            #pragma unroll
            for (int mt = 0; mt < 2; mt++)
                #pragma unroll
                for (int nt = 0; nt < 4; nt++) {
                    mma_tf32(acc[mt][nt], alo[mt], bhi[nt]);
                    mma_tf32(acc[mt][nt], ahi[mt], blo[nt]);
                    mma_tf32(acc[mt][nt], ahi[mt], bhi[nt]);
                }
        }
        __syncthreads();
    }

    #pragma unroll
    for (int mt = 0; mt < 2; mt++) {
        #pragma unroll
        for (int nt = 0; nt < 4; nt++) {
            const int r0 = bm + wm + mt * 16 + g;
            const int c0 = bn + wn + nt * 8 + tg * 2;
            #pragma unroll
            for (int ci = 0; ci < 4; ci++) {
                const int m = r0 + ((ci >> 1) ? 8 : 0);
                const int nn = c0 + (ci & 1);
                float v = acc[mt][nt][ci];
                if (bias) v += bias[nn];
                if (act == 1) {
                    v = (v >= 0.f) ? v : 0.01f * v;
                } else if (act == 2) {
                    float den = rnorm[m] * cnorm[nn];
                    v = (den != 0.f) ? v / den : 0.f;
                }
                C[(size_t)m * N + nn] = v;
            }
        }
    }
}

// ---------------- 3xTF32 GRU step kernels ----------------
// CTA: 64 rows x 32 gate-cols (x3 gates). grid (HID/32=8, BSZ/64=32), 128 thr.
#define GM 64
#define GN 32
#define GK 32
#define GPAD 36

__global__ void gru_mma0(const float* __restrict__ hin, float* __restrict__ hout,
                         const float* __restrict__ Whh, const float* __restrict__ bhh,
                         const float* __restrict__ inp, const float* __restrict__ Wih,
                         const float* __restrict__ bih, int t)
{
    __shared__ float As[GM][GPAD];          // raw h tile [row][k]
    __shared__ float Bs_hi[3 * GN][GPAD];   // pre-split Whh tile [n][k]
    __shared__ float Bs_lo[3 * GN][GPAD];
    __shared__ float xs[GM][DF];
    __shared__ float wih_s[GN][3 * DF];
    __shared__ float bih_s[3][GN];
    __shared__ float bhh_s[3][GN];

    const int bn = blockIdx.x * GN;
    const int bm = blockIdx.y * GM;
    const int tid = threadIdx.x;
    const int warp = tid >> 5, lane = tid & 31;
    const int wm = (warp & 1) * 32;          // 2 m-warps of 32 rows
    const int wn = (warp >> 1) * 16;         // 2 n-warps of 16 cols
    const int g = lane >> 2, tg = lane & 3;

    if (tid < 3 * GN) {
        const int gg = tid / GN, c = tid % GN;
        bih_s[gg][c] = bih[gg * HID + bn + c];
        bhh_s[gg][c] = bhh[gg * HID + bn + c];
    }
    for (int idx = tid; idx < GN * 3 * DF; idx += 128) {
        const int c = idx / (3 * DF), r = idx % (3 * DF);
        wih_s[c][r] = Wih[((r / DF) * HID + bn + c) * DF + (r % DF)];
    }
    for (int idx = tid; idx < GM * DF; idx += 128) {
        const int r = idx / DF, f = idx % DF;
        xs[r][f] = inp[(bm + r) * (DF * TT) + f * TT + t];
    }

    float acc[3][2][2][4];
    #pragma unroll
    for (int a = 0; a < 3; a++)
        #pragma unroll
        for (int b = 0; b < 2; b++)
            #pragma unroll
            for (int c = 0; c < 2; c++)
                #pragma unroll
                for (int d = 0; d < 4; d++) acc[a][b][c][d] = 0.f;

    for (int k0 = 0; k0 < HID; k0 += GK) {
        #pragma unroll
        for (int i = 0; i < 4; i++) {                 // A: 64x32 = 512 float4
            int idx = tid + i * 128;
            int r = idx >> 3, c4 = (idx & 7) * 4;
            float4 v = *(const float4*)(hin + (size_t)(bm + r) * HID + k0 + c4);
            *(float4*)&As[r][c4] = v;
        }
        #pragma unroll
        for (int i = 0; i < 6; i++) {                 // B: 96x32 = 768 float4, split hi/lo
            int idx = tid + i * 128;
            int nl = idx >> 3, c4 = (idx & 7) * 4;
            int grow = (nl >> 5) * HID + bn + (nl & 31);
            float4 v = *(const float4*)(Whh + (size_t)grow * HID + k0 + c4);
            uint32_t h0, l0, h1, l1, h2, l2, h3, l3;
            split_tf32(v.x, h0, l0); split_tf32(v.y, h1, l1);
            split_tf32(v.z, h2, l2); split_tf32(v.w, h3, l3);
            Bs_hi[nl][c4 + 0] = __uint_as_float(h0); Bs_lo[nl][c4 + 0] = __uint_as_float(l0);
            Bs_hi[nl][c4 + 1] = __uint_as_float(h1); Bs_lo[nl][c4 + 1] = __uint_as_float(l1);
            Bs_hi[nl][c4 + 2] = __uint_as_float(h2); Bs_lo[nl][c4 + 2] = __uint_as_float(l2);
            Bs_hi[nl][c4 + 3] = __uint_as_float(h3); Bs_lo[nl][c4 + 3] = __uint_as_float(l3);
        }
        __syncthreads();
        #pragma unroll
        for (int ks = 0; ks < GK / 8; ks++) {
            const int kb = ks * 8;
            uint32_t ahi[2][4], alo[2][4];
            #pragma unroll
            for (int mt = 0; mt < 2; mt++) {
                const int rb = wm + mt * 16;
                split_tf32(As[rb + g][kb + tg],         ahi[mt][0], alo[mt][0]);
                split_tf32(As[rb + g + 8][kb + tg],     ahi[mt][1], alo[mt][1]);
                split_tf32(As[rb + g][kb + tg + 4],     ahi[mt][2], alo[mt][2]);
                split_tf32(As[rb + g + 8][kb + tg + 4], ahi[mt][3], alo[mt][3]);
            }
            #pragma unroll
            for (int gg = 0; gg < 3; gg++) {
                uint32_t bh[2][2], bl[2][2];
                #pragma unroll
                for (int nt = 0; nt < 2; nt++) {
                    const int n = gg * GN + wn + nt * 8 + g;
                    bh[nt][0] = __float_as_uint(Bs_hi[n][kb + tg]);
                    bh[nt][1] = __float_as_uint(Bs_hi[n][kb + tg + 4]);
                    bl[nt][0] = __float_as_uint(Bs_lo[n][kb + tg]);
                    bl[nt][1] = __float_as_uint(Bs_lo[n][kb + tg + 4]);
                }
                #pragma unroll
                for (int mt = 0; mt < 2; mt++)
                    #pragma unroll
                    for (int nt = 0; nt < 2; nt++) {
                        mma_tf32(acc[gg][mt][nt], alo[mt], bh[nt]);
                        mma_tf32(acc[gg][mt][nt], ahi[mt], bl[nt]);
                        mma_tf32(acc[gg][mt][nt], ahi[mt], bh[nt]);
                    }
            }
        }
        __syncthreads();
    }

    #pragma unroll
    for (int mt = 0; mt < 2; mt++) {
        #pragma unroll
        for (int nt = 0; nt < 2; nt++) {
            #pragma unroll
            for (int ci = 0; ci < 4; ci++) {
                const int rl = wm + mt * 16 + g + ((ci >> 1) ? 8 : 0);
                const int cl = wn + nt * 8 + tg * 2 + (ci & 1);
                const int row = bm + rl, col = bn + cl;
                float xr = bih_s[0][cl], xz = bih_s[1][cl], xn = bih_s[2][cl];
                #pragma unroll
                for (int f = 0; f < DF; f++) {
                    const float xv = xs[rl][f];
                    xr += xv * wih_s[cl][f];
                    xz += xv * wih_s[cl][DF + f];
                    xn += xv * wih_s[cl][2 * DF + f];
                }
                const float r  = sigmoidf_(xr + acc[0][mt][nt][ci] + bhh_s[0][cl]);
                const float z  = sigmoidf_(xz + acc[1][mt][nt][ci] + bhh_s[1][cl]);
                const float nn = tanhf(xn + r * (acc[2][mt][nt][ci] + bhh_s[2][cl]));
                const float ho = hin[(size_t)row * HID + col];
                const float hv = (1.f - z) * nn + z * ho;
                hout[(size_t)row * HID + col] = hv;
                g_hs[((size_t)row * TT + t) * HID + col] = hv;
            }
        }
    }
}

__global__ void gru_mma1(const float* __restrict__ hin, float* __restrict__ hout,
                         const float* __restrict__ Whh, const float* __restrict__ bhh, int t)
{
    __shared__ float As[GM][GPAD];
    __shared__ float Bs_hi[3 * GN][GPAD];
    __shared__ float Bs_lo[3 * GN][GPAD];
    __shared__ float bhh_s[3][GN];

    const int bn = blockIdx.x * GN;
    const int bm = blockIdx.y * GM;
    const int tid = threadIdx.x;
    const int warp = tid >> 5, lane = tid & 31;
    const int wm = (warp & 1) * 32;
    const int wn = (warp >> 1) * 16;
    const int g = lane >> 2, tg = lane & 3;

    if (tid < 3 * GN) {
        const int gg = tid / GN, c = tid % GN;
        bhh_s[gg][c] = bhh[gg * HID + bn + c];
    }

    float acc[3][2][2][4];
    #pragma unroll
    for (int a = 0; a < 3; a++)
        #pragma unroll
        for (int b = 0; b < 2; b++)
            #pragma unroll
            for (int c = 0; c < 2; c++)
                #pragma unroll
                for (int d = 0; d < 4; d++) acc[a][b][c][d] = 0.f;

    for (int k0 = 0; k0 < HID; k0 += GK) {
        #pragma unroll
        for (int i = 0; i < 4; i++) {
            int idx = tid + i * 128;
            int r = idx >> 3, c4 = (idx & 7) * 4;
            float4 v = *(const float4*)(hin + (size_t)(bm + r) * HID + k0 + c4);
            *(float4*)&As[r][c4] = v;
        }
        #pragma unroll
        for (int i = 0; i < 6; i++) {
            int idx = tid + i * 128;
            int nl = idx >> 3, c4 = (idx & 7) * 4;
            int grow = (nl >> 5) * HID + bn + (nl & 31);
            float4 v = *(const float4*)(Whh + (size_t)grow * HID + k0 + c4);
            uint32_t h0, l0, h1, l1, h2, l2, h3, l3;
            split_tf32(v.x, h0, l0); split_tf32(v.y, h1, l1);
            split_tf32(v.z, h2, l2); split_tf32(v.w, h3, l3);
            Bs_hi[nl][c4 + 0] = __uint_as_float(h0); Bs_lo[nl][c4 + 0] = __uint_as_float(l0);
            Bs_hi[nl][c4 + 1] = __uint_as_float(h1); Bs_lo[nl][c4 + 1] = __uint_as_float(l1);
            Bs_hi[nl][c4 + 2] = __uint_as_float(h2); Bs_lo[nl][c4 + 2] = __uint_as_float(l2);
            Bs_hi[nl][c4 + 3] = __uint_as_float(h3); Bs_lo[nl][c4 + 3] = __uint_as_float(l3);
        }
        __syncthreads();
        #pragma unroll
        for (int ks = 0; ks < GK / 8; ks++) {
            const int kb = ks * 8;
            uint32_t ahi[2][4], alo[2][4];
            #pragma unroll
            for (int mt = 0; mt < 2; mt++) {
                const int rb = wm + mt * 16;
                split_tf32(As[rb + g][kb + tg],         ahi[mt][0], alo[mt][0]);
                split_tf32(As[rb + g + 8][kb + tg],     ahi[mt][1], alo[mt][1]);
                split_tf32(As[rb + g][kb + tg + 4],     ahi[mt][2], alo[mt][2]);
                split_tf32(As[rb + g + 8][kb + tg + 4], ahi[mt][3], alo[mt][3]);
            }
            #pragma unroll
            for (int gg = 0; gg < 3; gg++) {
                uint32_t bh[2][2], bl[2][2];
                #pragma unroll
                for (int nt = 0; nt < 2; nt++) {
                    const int n = gg * GN + wn + nt * 8 + g;
                    bh[nt][0] = __float_as_uint(Bs_hi[n][kb + tg]);
                    bh[nt][1] = __float_as_uint(Bs_hi[n][kb + tg + 4]);
                    bl[nt][0] = __float_as_uint(Bs_lo[n][kb + tg]);
                    bl[nt][1] = __float_as_uint(Bs_lo[n][kb + tg + 4]);
                }
                #pragma unroll
                for (int mt = 0; mt < 2; mt++)
                    #pragma unroll
                    for (int nt = 0; nt < 2; nt++) {
                        mma_tf32(acc[gg][mt][nt], alo[mt], bh[nt]);
                        mma_tf32(acc[gg][mt][nt], ahi[mt], bl[nt]);
                        mma_tf32(acc[gg][mt][nt], ahi[mt], bh[nt]);
                    }
            }
        }
        __syncthreads();
    }

    #pragma unroll
    for (int mt = 0; mt < 2; mt++) {
        #pragma unroll
        for (int nt = 0; nt < 2; nt++) {
            #pragma unroll
            for (int ci = 0; ci < 4; ci++) {
                const int rl = wm + mt * 16 + g + ((ci >> 1) ? 8 : 0);
                const int cl = wn + nt * 8 + tg * 2 + (ci & 1);
                const int row = bm + rl, col = bn + cl;
                const size_t xb = ((size_t)row * TT + t) * G3 + col;
                const float xr = g_xw1[xb];
                const float xz = g_xw1[xb + HID];
                const float xn = g_xw1[xb + 2 * HID];
                const float r  = sigmoidf_(xr + acc[0][mt][nt][ci] + bhh_s[0][cl]);
                const float z  = sigmoidf_(xz + acc[1][mt][nt][ci] + bhh_s[1][cl]);
                const float nn = tanhf(xn + r * (acc[2][mt][nt][ci] + bhh_s[2][cl]));
                const float ho = hin[(size_t)row * HID + col];
                hout[(size_t)row * HID + col] = (1.f - z) * nn + z * ho;
            }
        }
    }
}

// ---------------- small kernels ----------------
__global__ void mb_day_mean()
{
    const int b = blockIdx.x, h = threadIdx.x;
    float s = 0.f;
    for (int st = 0; st < 512; st++) s += g_mb[(b * 512 + st) * HID + h];
    g_mbday[b * HID + h] = s * (1.f / 512.f);
}

__global__ void day_topk(const float* __restrict__ thd)
{
    const int b = blockIdx.x;
    const int d = threadIdx.x;
    __shared__ float sim[NDAYS];
    const float* mbd = g_mbday + b * HID;
    float xn = 0.f;
    for (int i = 0; i < HID; i++) { float v = mbd[i]; xn += v * v; }
    xn = sqrtf(xn);
    if (d < NDAYS) {
        const float* yr = thd + d * HID;
        float yn = 0.f, dot = 0.f;
        for (int i = 0; i < HID; i++) { float y = yr[i]; yn += y * y; dot += mbd[i] * y; }
        const float den = xn * sqrtf(yn);
        sim[d] = (den != 0.f) ? dot / den : 0.f;
    }
    __syncthreads();
    if (d == 0) {
        for (int kk = 0; kk < KDAY; kk++) {
            float best = -1e30f; int bi = 0;
            for (int q = 0; q < NDAYS; q++)
                if (sim[q] > best) { best = sim[q]; bi = q; }
            g_dayidx[b * KDAY + kk] = bi;
            sim[bi] = -1e30f;
        }
    }
}

__global__ void make_rowmap()
{
    const int m = blockIdx.x * 256 + threadIdx.x;
    if (m < NSAMP) g_rowmap[m] = g_dayidx[m >> 9] * 512 + (m & 511);
}

__global__ void rownorm256(const float* __restrict__ X, float* __restrict__ out, int R)
{
    const int warp = (blockIdx.x * blockDim.x + threadIdx.x) >> 5;
    const int lane = threadIdx.x & 31;
    if (warp >= R) return;
    const float* r = X + (size_t)warp * HID;
    float s = 0.f;
    for (int i = lane; i < HID; i += 32) { float v = r[i]; s += v * v; }
    #pragma unroll
    for (int o = 16; o > 0; o >>= 1) s += __shfl_xor_sync(0xffffffffu, s, o);
    if (lane == 0) out[warp] = sqrtf(s);
}

__global__ void neigh_topk()
{
    const int n = blockIdx.x;
    const int tid = threadIdx.x;
    const float* row = g_cs + (size_t)n * NSAMP;

    float tv[NNB]; int ti[NNB];
    #pragma unroll
    for (int i = 0; i < NNB; i++) { tv[i] = -1e30f; ti[i] = 0x7fffffff; }

    for (int it = 0; it < NSAMP / 256; it++) {
        const int idx = tid + it * 256;
        const float v = row[idx];
        if (v > tv[NNB - 1]) {
            int p = NNB - 1;
            while (p > 0 && tv[p - 1] < v) { tv[p] = tv[p - 1]; ti[p] = ti[p - 1]; p--; }
            tv[p] = v; ti[p] = idx;
        }
    }

    __shared__ float sval[256 * NNB];
    __shared__ int   sidx[256 * NNB];
    __shared__ float rv[256];
    __shared__ int   rp[256];
    #pragma unroll
    for (int i = 0; i < NNB; i++) { sval[tid * NNB + i] = tv[i]; sidx[tid * NNB + i] = ti[i]; }
    __syncthreads();

    for (int kk = 0; kk < NNB; kk++) {
        float best = -1e30f; int bp = tid * NNB;
        #pragma unroll
        for (int i = 0; i < NNB; i++) {
            const float v = sval[tid * NNB + i];
            if (v > best) { best = v; bp = tid * NNB + i; }
        }
        rv[tid] = best; rp[tid] = bp;
        __syncthreads();
        for (int s = 128; s > 0; s >>= 1) {
            if (tid < s && rv[tid + s] > rv[tid]) { rv[tid] = rv[tid + s]; rp[tid] = rp[tid + s]; }
            __syncthreads();
        }
        if (tid == 0) {
            const int p = rp[0];
            g_vals[n * NNB + kk] = rv[0];
            g_nidx[n * NNB + kk] = sidx[p];
            sval[p] = -1e30f;
        }
        __syncthreads();
    }
}

__global__ void agg_fc(const float* __restrict__ fc_W, const float* __restrict__ fc_b,
                       float* __restrict__ y)
{
    const int n = blockIdx.x, h = threadIdx.x;
    float agg = 0.f;
    #pragma unroll
    for (int k = 0; k < NNB; k++) {
        const float v = g_vals[n * NNB + k] * (1.f / NNB);
        const int id = g_nidx[n * NNB + k];
        agg += v * g_kh[(size_t)id * HID + h];
    }
    float part = fc_W[h] * g_mb[n * HID + h] + fc_W[HID + h] * agg;
    __shared__ float red[256];
    red[h] = part;
    __syncthreads();
    for (int s = 128; s > 0; s >>= 1) {
        if (h < s) red[h] += red[h + s];
        __syncthreads();
    }
    if (h == 0) y[n] = red[0] + fc_b[0];
}

// ---------------- host ----------------
extern "C" void kernel_launch(void* const* d_in, const int* in_sizes, int n_in,
                              void* d_out, int out_size)
{
    const float* inp       = (const float*)d_in[0];
    const float* train_hid = (const float*)d_in[1];
    const float* thd       = (const float*)d_in[2];
    const float* W_ih0     = (const float*)d_in[3];
    const float* W_hh0     = (const float*)d_in[4];
    const float* b_ih0     = (const float*)d_in[5];
    const float* b_hh0     = (const float*)d_in[6];
    const float* W_ih1     = (const float*)d_in[7];
    const float* W_hh1     = (const float*)d_in[8];
    const float* b_ih1     = (const float*)d_in[9];
    const float* b_hh1     = (const float*)d_in[10];
    const float* lin0_W    = (const float*)d_in[11];
    const float* lin0_b    = (const float*)d_in[12];
    const float* lin1_W    = (const float*)d_in[13];
    const float* lin1_b    = (const float*)d_in[14];
    const float* lin2_W    = (const float*)d_in[15];
    const float* lin2_b    = (const float*)d_in[16];
    const float* proj1_W   = (const float*)d_in[17];
    const float* proj2_W   = (const float*)d_in[18];
    const float* fc_W      = (const float*)d_in[19];
    const float* fc_b      = (const float*)d_in[20];
    (void)in_sizes; (void)n_in; (void)out_size;

    float *p_h, *p_hb, *p_hs, *p_xw1, *p_mb1, *p_mb2, *p_mb, *p_kh, *p_khn, *p_q, *p_qn, *p_cs;
    int *p_rowmap;
    cudaGetSymbolAddress((void**)&p_h, g_h);
    cudaGetSymbolAddress((void**)&p_hb, g_hb);
    cudaGetSymbolAddress((void**)&p_hs, g_hs);
    cudaGetSymbolAddress((void**)&p_xw1, g_xw1);
    cudaGetSymbolAddress((void**)&p_mb1, g_mb1);
    cudaGetSymbolAddress((void**)&p_mb2, g_mb2);
    cudaGetSymbolAddress((void**)&p_mb, g_mb);
    cudaGetSymbolAddress((void**)&p_kh, g_kh);
    cudaGetSymbolAddress((void**)&p_khn, g_khn);
    cudaGetSymbolAddress((void**)&p_q, g_q);
    cudaGetSymbolAddress((void**)&p_qn, g_qn);
    cudaGetSymbolAddress((void**)&p_cs, g_cs);
    cudaGetSymbolAddress((void**)&p_rowmap, g_rowmap);

    const dim3 gru_grid(HID / GN, BSZ / GM);   // (8, 32)

    // ---- GRU layer 0 (tensor-core 3xTF32 fused steps, ping-pong h) ----
    cudaMemsetAsync(p_h, 0, BSZ * HID * sizeof(float));
    for (int t = 0; t < TT; t++) {
        const float* hi = (t & 1) ? p_hb : p_h;
        float*       ho = (t & 1) ? p_h  : p_hb;
        gru_mma0<<<gru_grid, 128>>>(hi, ho, W_hh0, b_hh0, inp, W_ih0, b_ih0, t);
    }

    // ---- layer-1 input gates: one big 3xTF32 GEMM ----
    gemm_x<<<dim3(G3 / XBN, (BSZ * TT) / XBM), 256>>>(p_hs, W_ih1, b_ih1, p_xw1,
                                                      BSZ * TT, G3, HID, 0, nullptr, nullptr, nullptr);

    // ---- GRU layer 1 ----
    cudaMemsetAsync(p_h, 0, BSZ * HID * sizeof(float));
    for (int t = 0; t < TT; t++) {
        const float* hi = (t & 1) ? p_hb : p_h;
        float*       ho = (t & 1) ? p_h  : p_hb;
        gru_mma1<<<gru_grid, 128>>>(hi, ho, W_hh1, b_hh1, t);
    }
    // final h (t=59) is in g_h

    // ---- MLP (leaky relu) ----
    gemm_x<<<dim3(512 / XBN, BSZ / XBM), 256>>>(p_h, lin0_W, lin0_b, p_mb1,
                                                BSZ, 512, HID, 1, nullptr, nullptr, nullptr);
    gemm_x<<<dim3(512 / XBN, BSZ / XBM), 256>>>(p_mb1, lin1_W, lin1_b, p_mb2,
                                                BSZ, 512, 512, 1, nullptr, nullptr, nullptr);
    gemm_x<<<dim3(HID / XBN, BSZ / XBM), 256>>>(p_mb2, lin2_W, lin2_b, p_mb,
                                                BSZ, HID, 512, 1, nullptr, nullptr, nullptr);

    // ---- day similarity + gather ----
    mb_day_mean<<<4, HID>>>();
    day_topk<<<4, 256>>>(thd);
    make_rowmap<<<NSAMP / 256, 256>>>();
    gemm_x<<<dim3(HID / XBN, NSAMP / XBM), 256>>>(train_hid, proj2_W, nullptr, p_kh,
                                                  NSAMP, HID, HID, 0, p_rowmap, nullptr, nullptr);
    rownorm256<<<(NSAMP * 32) / 256, 256>>>(p_kh, p_khn, NSAMP);

    // ---- queries + cosine sim + neighbor aggregation ----
    gemm_x<<<dim3(HID / XBN, BSZ / XBM), 256>>>(p_mb, proj1_W, nullptr, p_q,
                                                BSZ, HID, HID, 0, nullptr, nullptr, nullptr);
    rownorm256<<<(BSZ * 32) / 256, 256>>>(p_q, p_qn, BSZ);
    gemm_x<<<dim3(NSAMP / XBN, BSZ / XBM), 256>>>(p_q, p_kh, nullptr, p_cs,
                                                  BSZ, NSAMP, HID, 2, nullptr, p_qn, p_khn);
    neigh_topk<<<BSZ, 256>>>();
    agg_fc<<<BSZ, 256>>>(fc_W, fc_b, (float*)d_out);
}